// round 15
// baseline (speedup 1.0000x reference)
#include <cuda_runtime.h>
#include <cuda_bf16.h>
#include <cstdint>

#define D   128
#define H   8
#define DH  16
#define DF  512
#define NQ_MAX  20000
#define NKV_MAX 20000
#define E_MAX   640000

// ---------------- scratch (device globals; no allocations allowed) ----------
__device__ float g_q[NQ_MAX * D];
__device__ float g_k[NKV_MAX * D];
__device__ float g_v[NKV_MAX * D];
__device__ float g_feat[NQ_MAX * D];
__device__ float g_ffs[4 * NQ_MAX * D];     // W2 split-K partial sums (4 slices)

__device__ __align__(128) __nv_bfloat16 g_qf_hi[NQ_MAX * D];
__device__ __align__(128) __nv_bfloat16 g_qf_lo[NQ_MAX * D];
__device__ __align__(128) __nv_bfloat16 g_kvf_hi[NKV_MAX * D];
__device__ __align__(128) __nv_bfloat16 g_kvf_lo[NKV_MAX * D];
__device__ __align__(128) __nv_bfloat16 g_attn_hi[NQ_MAX * D];
__device__ __align__(128) __nv_bfloat16 g_attn_lo[NQ_MAX * D];
__device__ __align__(128) __nv_bfloat16 g_feat_hi[NQ_MAX * D];
__device__ __align__(128) __nv_bfloat16 g_feat_lo[NQ_MAX * D];
__device__ __align__(128) __nv_bfloat16 g_hid_hi[NQ_MAX * DF];
__device__ __align__(128) __nv_bfloat16 g_hid_lo[NQ_MAX * DF];
__device__ __align__(128) __nv_bfloat16 g_Wq_hi[D * D],  g_Wq_lo[D * D];
__device__ __align__(128) __nv_bfloat16 g_Wk_hi[D * D],  g_Wk_lo[D * D];
__device__ __align__(128) __nv_bfloat16 g_Wv_hi[D * D],  g_Wv_lo[D * D];
__device__ __align__(128) __nv_bfloat16 g_Wo_hi[D * D],  g_Wo_lo[D * D];
__device__ __align__(128) __nv_bfloat16 g_W1_hi[DF * D], g_W1_lo[DF * D];
__device__ __align__(128) __nv_bfloat16 g_W2_hi[D * DF], g_W2_lo[D * DF];

// CSR scratch (g_cnt must be zero at kernel entry; scan restores zeros)
__device__ int g_cnt[NQ_MAX];
__device__ int g_off[NQ_MAX + 1];
__device__ int g_cursor[NQ_MAX];
__device__ int g_slist[E_MAX];

// ---------------- helpers ------------------------------------------------------
__device__ __forceinline__ uint32_t smem_u32(const void* p) {
    uint32_t a;
    asm("{ .reg .u64 t; cvta.to.shared.u64 t, %1; cvt.u32.u64 %0, t; }" : "=r"(a) : "l"(p));
    return a;
}
__device__ __forceinline__ void f32_hilo(float x, __nv_bfloat16& h, __nv_bfloat16& l) {
    h = __float2bfloat16(x);
    l = __float2bfloat16(x - __bfloat162float(h));
}
__device__ __forceinline__ void mma16816(float* c, const uint32_t* a, const uint32_t* b) {
    asm volatile(
        "mma.sync.aligned.m16n8k16.row.col.f32.bf16.bf16.f32 "
        "{%0,%1,%2,%3}, {%4,%5,%6,%7}, {%8,%9}, {%0,%1,%2,%3};"
        : "+f"(c[0]), "+f"(c[1]), "+f"(c[2]), "+f"(c[3])
        : "r"(a[0]), "r"(a[1]), "r"(a[2]), "r"(a[3]), "r"(b[0]), "r"(b[1]));
}
__device__ __forceinline__ void ldsm4(uint32_t* r, uint32_t a) {
    asm volatile("ldmatrix.sync.aligned.m8n8.x4.shared.b16 {%0,%1,%2,%3}, [%4];"
                 : "=r"(r[0]), "=r"(r[1]), "=r"(r[2]), "=r"(r[3]) : "r"(a));
}

// ---------------- fused conversions (float4) + histogram -----------------------
__global__ void conv_hist(const float* __restrict__ qf, const float* __restrict__ kvf,
                          const float* __restrict__ Wq, const float* __restrict__ Wk,
                          const float* __restrict__ Wv, const float* __restrict__ Wo,
                          const float* __restrict__ W1, const float* __restrict__ W2,
                          const int* __restrict__ dst,
                          int nq4, int ntot4, int E) {
    int i = blockIdx.x * blockDim.x + threadIdx.x;
    if (i < ntot4 + 49152) {
        const float* srcp; __nv_bfloat16 *ho, *lo_; size_t r4;
        if (i < ntot4) {
            if (i < nq4) { srcp = qf;  r4 = i;       ho = g_qf_hi;  lo_ = g_qf_lo; }
            else         { srcp = kvf; r4 = i - nq4; ho = g_kvf_hi; lo_ = g_kvf_lo; }
        } else {
            int w = i - ntot4;
            if (w < 16384) {
                int which = w >> 12; r4 = w & 4095;
                if (which == 0)      { srcp = Wq; ho = g_Wq_hi; lo_ = g_Wq_lo; }
                else if (which == 1) { srcp = Wk; ho = g_Wk_hi; lo_ = g_Wk_lo; }
                else if (which == 2) { srcp = Wv; ho = g_Wv_hi; lo_ = g_Wv_lo; }
                else                 { srcp = Wo; ho = g_Wo_hi; lo_ = g_Wo_lo; }
            } else if (w < 32768) { srcp = W1; r4 = w - 16384; ho = g_W1_hi; lo_ = g_W1_lo; }
            else                  { srcp = W2; r4 = w - 32768; ho = g_W2_hi; lo_ = g_W2_lo; }
        }
        float4 x = *(const float4*)(srcp + r4 * 4);
        __nv_bfloat16 h[4], l[4];
        f32_hilo(x.x, h[0], l[0]); f32_hilo(x.y, h[1], l[1]);
        f32_hilo(x.z, h[2], l[2]); f32_hilo(x.w, h[3], l[3]);
        *(uint2*)(ho  + r4 * 4) = *(uint2*)h;
        *(uint2*)(lo_ + r4 * 4) = *(uint2*)l;
        return;
    }
    int e = i - ntot4 - 49152;
    if (e < E) atomicAdd(&g_cnt[dst[e]], 1);
}

// ---------------- tensor-core GEMM mainloop (acc in registers) -----------------
#define KSTB  80
#define BUF   (128 * KSTB)                 // 10240 bytes
#define STAGE (4 * BUF)                    // 40960 per stage
#define GEMM_SMEM (2 * STAGE)              // 81920 bytes

__device__ __forceinline__ void stage32(uint32_t sbase, int tid,
    const __nv_bfloat16* __restrict__ Ahi, const __nv_bfloat16* __restrict__ Alo,
    const __nv_bfloat16* __restrict__ Bhi, const __nv_bfloat16* __restrict__ Blo,
    int row0, int c0, int kc, int Kstride, int Nrows) {
#pragma unroll
    for (int j = 0; j < 8; j++) {
        int id  = tid + (j << 8);
        int buf = id >> 9;
        int rem = id & 511;
        int r   = rem >> 2;
        int c16 = rem & 3;
        const __nv_bfloat16* g;
        int rg;
        if (buf == 0)      { g = Ahi; rg = min(row0 + r, Nrows - 1); }
        else if (buf == 1) { g = Alo; rg = min(row0 + r, Nrows - 1); }
        else if (buf == 2) { g = Bhi; rg = c0 + r; }
        else               { g = Blo; rg = c0 + r; }
        uint32_t daddr = sbase + buf * BUF + r * KSTB + c16 * 16;
        unsigned long long gsrc =
            (unsigned long long)__cvta_generic_to_global(g + (size_t)rg * Kstride + kc + c16 * 8);
        asm volatile("cp.async.cg.shared.global [%0], [%1], 16;"
                     :: "r"(daddr), "l"(gsrc) : "memory");
    }
}

__device__ __forceinline__ void gemm_compute(
    char* smem,
    const __nv_bfloat16* __restrict__ Ahi, const __nv_bfloat16* __restrict__ Alo,
    const __nv_bfloat16* __restrict__ Bhi, const __nv_bfloat16* __restrict__ Blo,
    int Nrows, int Kstride, int Klen, int row0, int c0,
    float (&acc)[4][4][4]) {
    const uint32_t sb = smem_u32(smem);
    const int tid  = threadIdx.x;
    const int wid  = tid >> 5;
    const int lane = tid & 31;
    const int wr   = wid >> 2;
    const int wc   = wid & 3;

    const int a_off = ((lane & 7) + ((lane >> 3) & 1) * 8) * KSTB + (lane >> 4) * 16;
    const int b_off = ((lane & 7) + (lane >> 4) * 8) * KSTB + ((lane >> 3) & 1) * 16;

#pragma unroll
    for (int mi = 0; mi < 4; mi++)
#pragma unroll
        for (int ni = 0; ni < 4; ni++)
#pragma unroll
            for (int t = 0; t < 4; t++) acc[mi][ni][t] = 0.f;

    const int NC = Klen >> 5;
    stage32(sb, tid, Ahi, Alo, Bhi, Blo, row0, c0, 0, Kstride, Nrows);
    asm volatile("cp.async.commit_group;" ::: "memory");

    for (int ch = 0; ch < NC; ch++) {
        if (ch + 1 < NC) {
            stage32(sb + ((ch + 1) & 1) * STAGE, tid, Ahi, Alo, Bhi, Blo,
                    row0, c0, (ch + 1) << 5, Kstride, Nrows);
            asm volatile("cp.async.commit_group;" ::: "memory");
            asm volatile("cp.async.wait_group 1;" ::: "memory");
        } else {
            asm volatile("cp.async.wait_group 0;" ::: "memory");
        }
        __syncthreads();

        const uint32_t uAh = sb + (ch & 1) * STAGE;
        const uint32_t uAl = uAh + BUF;
        const uint32_t uBh = uAh + 2 * BUF;
        const uint32_t uBl = uAh + 3 * BUF;

#pragma unroll
        for (int ks = 0; ks < 2; ks++) {
            const int kbyte = ks << 5;
            uint32_t bh[2][4], bl[2][4];
#pragma unroll
            for (int p = 0; p < 2; p++) {
                uint32_t bbase = (uint32_t)((wc * 32 + p * 16) * KSTB + kbyte + b_off);
                ldsm4(bh[p], uBh + bbase);
                ldsm4(bl[p], uBl + bbase);
            }
#pragma unroll
            for (int mi = 0; mi < 4; mi++) {
                uint32_t abase = (uint32_t)((wr * 64 + mi * 16) * KSTB + kbyte + a_off);
                uint32_t ah[4], al[4];
                ldsm4(ah, uAh + abase);
                ldsm4(al, uAl + abase);
#pragma unroll
                for (int ni = 0; ni < 4; ni++) {
                    const uint32_t* pbh = &bh[ni >> 1][(ni & 1) * 2];
                    const uint32_t* pbl = &bl[ni >> 1][(ni & 1) * 2];
                    mma16816(acc[mi][ni], ah, pbh);
                    mma16816(acc[mi][ni], ah, pbl);
                    mma16816(acc[mi][ni], al, pbh);
                }
            }
        }
        __syncthreads();
    }
}

template<bool BIAS, bool RELU, bool WF32, bool WHILO>
__device__ __forceinline__ void gemm_body(
    char* smem,
    const __nv_bfloat16* __restrict__ Ahi, const __nv_bfloat16* __restrict__ Alo,
    const __nv_bfloat16* __restrict__ Bhi, const __nv_bfloat16* __restrict__ Blo,
    const float* __restrict__ bias,
    float* __restrict__ outf, __nv_bfloat16* __restrict__ outhi,
    __nv_bfloat16* __restrict__ outlo, int Nrows, int C,
    int Kstride, int Klen, int row0, int c0) {
    float acc[4][4][4];
    gemm_compute(smem, Ahi, Alo, Bhi, Blo, Nrows, Kstride, Klen, row0, c0, acc);

    const int tid  = threadIdx.x;
    const int wid  = tid >> 5;
    const int lane = tid & 31;
    const int wr   = wid >> 2;
    const int wc   = wid & 3;
    const int gq   = lane >> 2;
    const int tg   = lane & 3;

#pragma unroll
    for (int mi = 0; mi < 4; mi++) {
#pragma unroll
        for (int half = 0; half < 2; half++) {
            int r = row0 + wr * 64 + mi * 16 + gq + half * 8;
            if (r >= Nrows) continue;
#pragma unroll
            for (int ni = 0; ni < 4; ni++) {
                int c = c0 + wc * 32 + ni * 8 + tg * 2;
                float v0 = acc[mi][ni][half * 2 + 0];
                float v1 = acc[mi][ni][half * 2 + 1];
                if (BIAS && bias != nullptr) { v0 += bias[c]; v1 += bias[c + 1]; }
                if (RELU) { v0 = fmaxf(v0, 0.f); v1 = fmaxf(v1, 0.f); }
                size_t o = (size_t)r * C + c;
                if (WF32) *(float2*)(outf + o) = make_float2(v0, v1);
                if (WHILO) {
                    __nv_bfloat16 h0, l0, h1, l1;
                    f32_hilo(v0, h0, l0); f32_hilo(v1, h1, l1);
                    __nv_bfloat162 hh; hh.x = h0; hh.y = h1;
                    __nv_bfloat162 ll; ll.x = l0; ll.y = l1;
                    *(__nv_bfloat162*)(outhi + o) = hh;
                    *(__nv_bfloat162*)(outlo + o) = ll;
                }
            }
        }
    }
}

// SPLITK4: grid.y = K-quarter; partial fp32 sums to outf + kh*kslice; bias only in slice 0.
template<bool BIAS, bool RELU, bool WF32, bool WHILO, bool SPLITK4>
__global__ void __launch_bounds__(256, 2)
gemm_mma(const __nv_bfloat16* __restrict__ Ahi, const __nv_bfloat16* __restrict__ Alo,
         const __nv_bfloat16* __restrict__ Bhi, const __nv_bfloat16* __restrict__ Blo,
         const float* __restrict__ bias,
         float* __restrict__ outf, size_t kslice,
         __nv_bfloat16* __restrict__ outhi, __nv_bfloat16* __restrict__ outlo,
         int Nrows, int C, int Kstride, int Klen) {
    extern __shared__ char smem[];
    if (SPLITK4) {
        int kh   = blockIdx.y;
        int koff = kh * Klen;
        float* of = outf + (size_t)kh * kslice;
        const float* b = kh ? nullptr : bias;
        gemm_body<BIAS, RELU, WF32, WHILO>(smem, Ahi + koff, Alo + koff,
                                           Bhi + koff, Blo + koff, b,
                                           of, outhi, outlo, Nrows, C,
                                           Kstride, Klen, blockIdx.x * 128, 0);
    } else {
        gemm_body<BIAS, RELU, WF32, WHILO>(smem, Ahi, Alo, Bhi, Blo, bias,
                                           outf, outhi, outlo, Nrows, C,
                                           Kstride, Klen, blockIdx.x * 128,
                                           blockIdx.y * 128);
    }
}

// ---------------- fused Wo GEMM + residual + LN1 -------------------------------
__global__ void __launch_bounds__(256, 2)
wo_ln(const float* __restrict__ qfeat, const float* __restrict__ gamma,
      const float* __restrict__ beta, int NQ) {
    extern __shared__ char smem[];
    const int row0 = blockIdx.x * 128;
    float acc[4][4][4];
    gemm_compute(smem, g_attn_hi, g_attn_lo, g_Wo_hi, g_Wo_lo, NQ, D, D, row0, 0, acc);

    const int tid  = threadIdx.x;
    const int wid  = tid >> 5;
    const int lane = tid & 31;
    const int wr   = wid >> 2;
    const int wc   = wid & 3;
    const int gq   = lane >> 2;
    const int tg   = lane & 3;

    float* sf = (float*)smem;              // 128 x 132 fp32 tile
#pragma unroll
    for (int mi = 0; mi < 4; mi++)
#pragma unroll
        for (int half = 0; half < 2; half++) {
            int r = wr * 64 + mi * 16 + gq + half * 8;
#pragma unroll
            for (int ni = 0; ni < 4; ni++) {
                int c = wc * 32 + ni * 8 + tg * 2;
                sf[r * 132 + c]     = acc[mi][ni][half * 2 + 0];
                sf[r * 132 + c + 1] = acc[mi][ni][half * 2 + 1];
            }
        }
    __syncthreads();

    float4 g4 = *(const float4*)(gamma + lane * 4);
    float4 b4 = *(const float4*)(beta  + lane * 4);
    for (int rr = 0; rr < 16; rr++) {
        int r  = wid * 16 + rr;
        int gr = row0 + r;
        if (gr >= NQ) break;
        float4 x = *(const float4*)(sf + r * 132 + lane * 4);
        float4 qv = *(const float4*)(qfeat + (size_t)gr * D + lane * 4);
        x.x += qv.x; x.y += qv.y; x.z += qv.z; x.w += qv.w;
        float s  = x.x + x.y + x.z + x.w;
        float s2 = x.x * x.x + x.y * x.y + x.z * x.z + x.w * x.w;
#pragma unroll
        for (int o = 16; o; o >>= 1) {
            s  += __shfl_xor_sync(0xffffffffu, s,  o);
            s2 += __shfl_xor_sync(0xffffffffu, s2, o);
        }
        float mu  = s * (1.f / 128.f);
        float var = s2 * (1.f / 128.f) - mu * mu;
        float inv = rsqrtf(var + 1e-5f);
        float4 y;
        y.x = (x.x - mu) * inv * g4.x + b4.x;
        y.y = (x.y - mu) * inv * g4.y + b4.y;
        y.z = (x.z - mu) * inv * g4.z + b4.z;
        y.w = (x.w - mu) * inv * g4.w + b4.w;
        size_t o_ = (size_t)gr * D + lane * 4;
        *(float4*)(g_feat + o_) = y;
        __nv_bfloat16 h[4], l[4];
        f32_hilo(y.x, h[0], l[0]); f32_hilo(y.y, h[1], l[1]);
        f32_hilo(y.z, h[2], l[2]); f32_hilo(y.w, h[3], l[3]);
        *(uint2*)(g_feat_hi + o_) = *(uint2*)h;
        *(uint2*)(g_feat_lo + o_) = *(uint2*)l;
    }
}

// CSR scan as a device function (256 threads); also re-zeroes cnt for replay
__device__ void scan_body(char* smem_raw, int* cnt, int* off, int* cursor, int n) {
    int* sc = (int*)smem_raw;
    __shared__ int wsum[8];
    const int tid  = threadIdx.x;
    const int lane = tid & 31;
    const int wid  = tid >> 5;

    for (int i = tid; i < n; i += 256) { sc[i] = cnt[i]; cnt[i] = 0; }
    __syncthreads();

    const int chunk = (n + 255) >> 8;
    const int s = min(tid * chunk, n);
    const int e = min(s + chunk, n);

    int sum = 0;
    for (int i = s; i < e; i++) sum += sc[i];

    int x = sum;
#pragma unroll
    for (int o = 1; o < 32; o <<= 1) {
        int y = __shfl_up_sync(0xffffffffu, x, o);
        if (lane >= o) x += y;
    }
    if (lane == 31) wsum[wid] = x;
    __syncthreads();
    int pre = 0;
    for (int w = 0; w < wid; w++) pre += wsum[w];

    int run = x - sum + pre;
    for (int i = s; i < e; i++) {
        int c = sc[i];
        sc[i] = run;
        run += c;
    }
    __syncthreads();
    for (int i = tid; i < n; i += 256) {
        int v = sc[i];
        off[i] = v;
        cursor[i] = v;
    }
    if (tid == 255) off[n] = run;
}

// fused q/k/v projections + single scan block (1D grid: 3*MT GEMM blocks + 1)
__global__ void __launch_bounds__(256, 2)
proj_scan(int NQ, int NKV, int MT, int* cnt, int* off, int* cursor) {
    extern __shared__ char smem[];
    int b = blockIdx.x;
    if (b < 3 * MT) {
        int which = b / MT;
        int row0  = (b % MT) * 128;
        if (which == 0) {
            if (row0 >= NQ) return;
            gemm_body<false, false, true, false>(smem, g_qf_hi, g_qf_lo, g_Wq_hi, g_Wq_lo,
                                                 nullptr, g_q, nullptr, nullptr, NQ, D, D, D, row0, 0);
        } else if (which == 1) {
            if (row0 >= NKV) return;
            gemm_body<false, false, true, false>(smem, g_kvf_hi, g_kvf_lo, g_Wk_hi, g_Wk_lo,
                                                 nullptr, g_k, nullptr, nullptr, NKV, D, D, D, row0, 0);
        } else {
            if (row0 >= NKV) return;
            gemm_body<false, false, true, false>(smem, g_kvf_hi, g_kvf_lo, g_Wv_hi, g_Wv_lo,
                                                 nullptr, g_v, nullptr, nullptr, NKV, D, D, D, row0, 0);
        }
    } else {
        scan_body(smem, cnt, off, cursor, NQ);
    }
}

// ---------------- CSR fill: 4 edges/thread for atomic MLP ---------------------
__global__ void fill_kernel(const int* __restrict__ dst, const int* __restrict__ src,
                            int* __restrict__ cursor, int* __restrict__ slist, int E) {
    int S = (E + 3) >> 2;
    int t = blockIdx.x * blockDim.x + threadIdx.x;
    if (t >= S) return;
    int e0 = t, e1 = t + S, e2 = t + 2 * S, e3 = t + 3 * S;
    bool b1 = e1 < E, b2 = e2 < E, b3 = e3 < E;
    int d0 = dst[e0];
    int d1 = b1 ? dst[e1] : 0;
    int d2 = b2 ? dst[e2] : 0;
    int d3 = b3 ? dst[e3] : 0;
    int r0 = src[e0];
    int r1 = b1 ? src[e1] : 0;
    int r2 = b2 ? src[e2] : 0;
    int r3 = b3 ? src[e3] : 0;
    int p0 = atomicAdd(&cursor[d0], 1);
    int p1 = b1 ? atomicAdd(&cursor[d1], 1) : 0;
    int p2 = b2 ? atomicAdd(&cursor[d2], 1) : 0;
    int p3 = b3 ? atomicAdd(&cursor[d3], 1) : 0;
    slist[p0] = r0;
    if (b1) slist[p1] = r1;
    if (b2) slist[p2] = r2;
    if (b3) slist[p3] = r3;
}

// ---------------- fused edge-softmax attention (two warps per dst node) -------
#define ASHIFT 20.0f
__global__ __launch_bounds__(256, 6)
void attn_gather(const float* __restrict__ k, const float* __restrict__ q,
                 const float* __restrict__ v, const int* __restrict__ slist,
                 const int* __restrict__ off,
                 __nv_bfloat16* __restrict__ out_hi, __nv_bfloat16* __restrict__ out_lo,
                 int NQ) {
    __shared__ float red[8][5 * 32];
    int gwarp = (blockIdx.x * blockDim.x + threadIdx.x) >> 5;
    int lane  = threadIdx.x & 31;
    int bwid  = threadIdx.x >> 5;
    int node  = gwarp >> 1;
    int half  = gwarp & 1;
    if (node >= NQ) return;

    float4 qv = *(const float4*)(q + (size_t)node * D + lane * 4);
    int i0 = off[node], i1 = off[node + 1];
    int mid = i0 + ((i1 - i0) >> 1);
    int lo  = half ? mid : i0;
    int hi  = half ? i1  : mid;

    float sA = 0.f, sB = 0.f;
    float4 aA = make_float4(0.f, 0.f, 0.f, 0.f);
    float4 aB = make_float4(0.f, 0.f, 0.f, 0.f);

    int i = lo;
    for (; i + 1 < hi; i += 2) {
        int s0 = slist[i], s1 = slist[i + 1];
        float4 k0 = *(const float4*)(k + (size_t)s0 * D + lane * 4);
        float4 k1 = *(const float4*)(k + (size_t)s1 * D + lane * 4);
        float4 v0 = *(const float4*)(v + (size_t)s0 * D + lane * 4);
        float4 v1 = *(const float4*)(v + (size_t)s1 * D + lane * 4);
        float d0 = k0.x * qv.x + k0.y * qv.y + k0.z * qv.z + k0.w * qv.w;
        float d1 = k1.x * qv.x + k1.y * qv.y + k1.z * qv.z + k1.w * qv.w;
        d0 += __shfl_xor_sync(0xffffffffu, d0, 1);
        d1 += __shfl_xor_sync(0xffffffffu, d1, 1);
        d0 += __shfl_xor_sync(0xffffffffu, d0, 2);
        d1 += __shfl_xor_sync(0xffffffffu, d1, 2);
        float p0 = __expf(d0 * 0.25f - ASHIFT);
        float p1 = __expf(d1 * 0.25f - ASHIFT);
        sA += p0;
        sB += p1;
        aA.x += p0 * v0.x;  aB.x += p1 * v1.x;
        aA.y += p0 * v0.y;  aB.y += p1 * v1.y;
        aA.z += p0 * v0.z;  aB.z += p1 * v1.z;
        aA.w += p0 * v0.w;  aB.w += p1 * v1.w;
    }
    if (i < hi) {
        int s0 = slist[i];
        float4 k0 = *(const float4*)(k + (size_t)s0 * D + lane * 4);
        float4 v0 = *(const float4*)(v + (size_t)s0 * D + lane * 4);
        float d0 = k0.x * qv.x + k0.y * qv.y + k0.z * qv.z + k0.w * qv.w;
        d0 += __shfl_xor_sync(0xffffffffu, d0, 1);
        d0 += __shfl_xor_sync(0xffffffffu, d0, 2);
        float p0 = __expf(d0 * 0.25f - ASHIFT);
        sA += p0;
        aA.x += p0 * v0.x; aA.y += p0 * v0.y;
        aA.z += p0 * v0.z; aA.w += p0 * v0.w;
    }
    float s = sA + sB;
    float4 acc;
    acc.x = aA.x + aB.x;
    acc.y = aA.y + aB.y;
    acc.z = aA.z + aB.z;
    acc.w = aA.w + aB.w;

    float* slot = red[bwid];
    slot[0 * 32 + lane] = s;
    slot[1 * 32 + lane] = acc.x;
    slot[2 * 32 + lane] = acc.y;
    slot[3 * 32 + lane] = acc.z;
    slot[4 * 32 + lane] = acc.w;
    __syncthreads();
    if (half == 0) {
        const float* part = red[bwid ^ 1];
        s     += part[0 * 32 + lane];
        acc.x += part[1 * 32 + lane];
        acc.y += part[2 * 32 + lane];
        acc.z += part[3 * 32 + lane];
        acc.w += part[4 * 32 + lane];

        float inv = (s > 0.f) ? (1.f / s) : 0.f;
        float4 o = make_float4(acc.x * inv, acc.y * inv, acc.z * inv, acc.w * inv);
        __nv_bfloat16 h[4], l[4];
        f32_hilo(o.x, h[0], l[0]); f32_hilo(o.y, h[1], l[1]);
        f32_hilo(o.z, h[2], l[2]); f32_hilo(o.w, h[3], l[3]);
        size_t ob = (size_t)node * D + lane * 4;
        *(uint2*)(out_hi + ob) = *(uint2*)h;
        *(uint2*)(out_lo + ob) = *(uint2*)l;
    }
}

// ---------------- residual add (1 + 4 split-K slices) + layernorm -------------
__global__ void add_ln_kernel(const float* __restrict__ a, const float* __restrict__ ffs,
                              size_t kslice,
                              const float* __restrict__ gamma, const float* __restrict__ beta,
                              float* __restrict__ out) {
    int row = blockIdx.x;
    int t   = threadIdx.x;
    size_t idx = (size_t)row * D + t;
    float x = a[idx] + ffs[idx] + ffs[idx + kslice] +
              ffs[idx + 2 * kslice] + ffs[idx + 3 * kslice];
    float s = x, s2 = x * x;
#pragma unroll
    for (int off = 16; off; off >>= 1) {
        s  += __shfl_xor_sync(0xffffffffu, s,  off);
        s2 += __shfl_xor_sync(0xffffffffu, s2, off);
    }
    __shared__ float ps[4], ps2[4];
    if ((t & 31) == 0) { ps[t >> 5] = s; ps2[t >> 5] = s2; }
    __syncthreads();
    s  = ps[0]  + ps[1]  + ps[2]  + ps[3];
    s2 = ps2[0] + ps2[1] + ps2[2] + ps2[3];
    float mu  = s * (1.f / 128.f);
    float var = s2 * (1.f / 128.f) - mu * mu;
    float invs = rsqrtf(var + 1e-5f);
    out[idx] = (x - mu) * invs * gamma[t] + beta[t];
}

// ---------------- launch -----------------------------------------------------
extern "C" void kernel_launch(void* const* d_in, const int* in_sizes, int n_in,
                              void* d_out, int out_size) {
    const float* q_feat  = (const float*)d_in[0];
    const float* kv_feat = (const float*)d_in[1];
    const int*   src     = (const int*)d_in[2];
    const int*   dst     = (const int*)d_in[3];
    const float* Wq      = (const float*)d_in[4];
    const float* Wk      = (const float*)d_in[5];
    const float* Wv      = (const float*)d_in[6];
    const float* Wo      = (const float*)d_in[7];
    const float* W1      = (const float*)d_in[8];
    const float* bf1     = (const float*)d_in[9];
    const float* W2      = (const float*)d_in[10];
    const float* bf2     = (const float*)d_in[11];
    const float* ln1_g   = (const float*)d_in[12];
    const float* ln1_b   = (const float*)d_in[13];
    const float* ln2_g   = (const float*)d_in[14];
    const float* ln2_b   = (const float*)d_in[15];

    const int NQ  = in_sizes[0] / D;
    const int NKV = in_sizes[1] / D;
    const int E   = in_sizes[2];

    float *qp, *kp, *vp, *featp, *ffsp;
    __nv_bfloat16 *ath, *atl, *fth, *ftl, *hdh, *hdl;
    __nv_bfloat16 *w1h, *w1l, *w2h, *w2l;
    int *cntp, *offp, *curp, *slistp;
    cudaGetSymbolAddress((void**)&qp,    g_q);
    cudaGetSymbolAddress((void**)&kp,    g_k);
    cudaGetSymbolAddress((void**)&vp,    g_v);
    cudaGetSymbolAddress((void**)&featp, g_feat);
    cudaGetSymbolAddress((void**)&ffsp,  g_ffs);
    cudaGetSymbolAddress((void**)&ath,   g_attn_hi); cudaGetSymbolAddress((void**)&atl, g_attn_lo);
    cudaGetSymbolAddress((void**)&fth,   g_feat_hi); cudaGetSymbolAddress((void**)&ftl, g_feat_lo);
    cudaGetSymbolAddress((void**)&hdh,   g_hid_hi);  cudaGetSymbolAddress((void**)&hdl, g_hid_lo);
    cudaGetSymbolAddress((void**)&w1h,   g_W1_hi);   cudaGetSymbolAddress((void**)&w1l, g_W1_lo);
    cudaGetSymbolAddress((void**)&w2h,   g_W2_hi);   cudaGetSymbolAddress((void**)&w2l, g_W2_lo);
    cudaGetSymbolAddress((void**)&cntp,  g_cnt);
    cudaGetSymbolAddress((void**)&offp,  g_off);
    cudaGetSymbolAddress((void**)&curp,  g_cursor);
    cudaGetSymbolAddress((void**)&slistp, g_slist);

    cudaFuncSetAttribute(proj_scan,
                         cudaFuncAttributeMaxDynamicSharedMemorySize, GEMM_SMEM);
    cudaFuncSetAttribute(wo_ln,
                         cudaFuncAttributeMaxDynamicSharedMemorySize, GEMM_SMEM);
    cudaFuncSetAttribute(gemm_mma<true,  true,  false, true,  false>,
                         cudaFuncAttributeMaxDynamicSharedMemorySize, GEMM_SMEM);
    cudaFuncSetAttribute(gemm_mma<true,  false, true,  false, true>,
                         cudaFuncAttributeMaxDynamicSharedMemorySize, GEMM_SMEM);

    const int MTq  = (NQ + 127) / 128;
    const int MTkv = (NKV + 127) / 128;
    const int MTmax = MTq > MTkv ? MTq : MTkv;
    const size_t kslice = (size_t)NQ_MAX * D;

    // (0) fused conversions (vectorized) + histogram
    int nq4   = NQ * D / 4;
    int ntot4 = (NQ + NKV) * D / 4;
    int ch_threads = ntot4 + 49152 + E;
    conv_hist<<<(ch_threads + 255) / 256, 256>>>(q_feat, kv_feat, Wq, Wk, Wv, Wo, W1, W2,
                                                 dst, nq4, ntot4, E);
    // (1) fused q/k/v projections + scan
    proj_scan<<<3 * MTmax + 1, 256, GEMM_SMEM>>>(NQ, NKV, MTmax, cntp, offp, curp);
    // (2) CSR fill (4 edges/thread)
    int fthreads = (E + 3) / 4;
    fill_kernel<<<(fthreads + 255) / 256, 256>>>(dst, src, curp, slistp, E);
    // (3) fused edge-softmax attention (2 warps/node)  <- ncu capture slot
    int ablocks = (NQ * 2 * 32 + 255) / 256;
    attn_gather<<<ablocks, 256>>>(kp, qp, vp, slistp, offp, ath, atl, NQ);

    // (4) fused Wo GEMM + residual + LN1
    wo_ln<<<MTq, 256, GEMM_SMEM>>>(q_feat, ln1_g, ln1_b, NQ);

    // FFN: W1 (no split, 4 col tiles), W2 (split-K: 4 slices of 128)
    gemm_mma<true, true, false, true, false><<<dim3(MTq, 4), 256, GEMM_SMEM>>>(
        fth, ftl, w1h, w1l, bf1, nullptr, 0, hdh, hdl, NQ, DF, D, D);
    gemm_mma<true, false, true, false, true><<<dim3(MTq, 4), 256, GEMM_SMEM>>>(
        hdh, hdl, w2h, w2l, bf2, ffsp, kslice, nullptr, nullptr, NQ, D, DF, 128);

    // final residual LN -> output
    add_ln_kernel<<<NQ, 128>>>(featp, ffsp, kslice, ln2_g, ln2_b, (float*)d_out);
}

// round 16
// speedup vs baseline: 1.0368x; 1.0368x over previous
#include <cuda_runtime.h>
#include <cuda_bf16.h>
#include <cstdint>

#define D   128
#define H   8
#define DH  16
#define DF  512
#define NQ_MAX  20000
#define NKV_MAX 20000
#define E_MAX   640000

// ---------------- scratch (device globals; no allocations allowed) ----------
__device__ float g_q[NQ_MAX * D];
__device__ float g_k[NKV_MAX * D];
__device__ float g_v[NKV_MAX * D];
__device__ float g_feat[NQ_MAX * D];
__device__ float g_ffs[4 * NQ_MAX * D];     // W2 split-K partial sums (4 slices)

__device__ __align__(128) __nv_bfloat16 g_qf_hi[NQ_MAX * D];
__device__ __align__(128) __nv_bfloat16 g_qf_lo[NQ_MAX * D];
__device__ __align__(128) __nv_bfloat16 g_kvf_hi[NKV_MAX * D];
__device__ __align__(128) __nv_bfloat16 g_kvf_lo[NKV_MAX * D];
__device__ __align__(128) __nv_bfloat16 g_attn_hi[NQ_MAX * D];
__device__ __align__(128) __nv_bfloat16 g_attn_lo[NQ_MAX * D];
__device__ __align__(128) __nv_bfloat16 g_feat_hi[NQ_MAX * D];
__device__ __align__(128) __nv_bfloat16 g_feat_lo[NQ_MAX * D];
__device__ __align__(128) __nv_bfloat16 g_hid_hi[NQ_MAX * DF];
__device__ __align__(128) __nv_bfloat16 g_hid_lo[NQ_MAX * DF];
__device__ __align__(128) __nv_bfloat16 g_Wq_hi[D * D],  g_Wq_lo[D * D];
__device__ __align__(128) __nv_bfloat16 g_Wk_hi[D * D],  g_Wk_lo[D * D];
__device__ __align__(128) __nv_bfloat16 g_Wv_hi[D * D],  g_Wv_lo[D * D];
__device__ __align__(128) __nv_bfloat16 g_Wo_hi[D * D],  g_Wo_lo[D * D];
__device__ __align__(128) __nv_bfloat16 g_W1_hi[DF * D], g_W1_lo[DF * D];
__device__ __align__(128) __nv_bfloat16 g_W2_hi[D * DF], g_W2_lo[D * DF];

// CSR scratch (g_cnt must be zero at kernel entry; scan restores zeros)
__device__ int g_cnt[NQ_MAX];
__device__ int g_off[NQ_MAX + 1];
__device__ int g_cursor[NQ_MAX];
__device__ int g_slist[E_MAX];

// ---------------- helpers ------------------------------------------------------
__device__ __forceinline__ uint32_t smem_u32(const void* p) {
    uint32_t a;
    asm("{ .reg .u64 t; cvta.to.shared.u64 t, %1; cvt.u32.u64 %0, t; }" : "=r"(a) : "l"(p));
    return a;
}
__device__ __forceinline__ void f32_hilo(float x, __nv_bfloat16& h, __nv_bfloat16& l) {
    h = __float2bfloat16(x);
    l = __float2bfloat16(x - __bfloat162float(h));
}
__device__ __forceinline__ void mma16816(float* c, const uint32_t* a, const uint32_t* b) {
    asm volatile(
        "mma.sync.aligned.m16n8k16.row.col.f32.bf16.bf16.f32 "
        "{%0,%1,%2,%3}, {%4,%5,%6,%7}, {%8,%9}, {%0,%1,%2,%3};"
        : "+f"(c[0]), "+f"(c[1]), "+f"(c[2]), "+f"(c[3])
        : "r"(a[0]), "r"(a[1]), "r"(a[2]), "r"(a[3]), "r"(b[0]), "r"(b[1]));
}
__device__ __forceinline__ void ldsm4(uint32_t* r, uint32_t a) {
    asm volatile("ldmatrix.sync.aligned.m8n8.x4.shared.b16 {%0,%1,%2,%3}, [%4];"
                 : "=r"(r[0]), "=r"(r[1]), "=r"(r[2]), "=r"(r[3]) : "r"(a));
}

// ---------------- fused conversions (float4) + histogram -----------------------
__global__ void conv_hist(const float* __restrict__ qf, const float* __restrict__ kvf,
                          const float* __restrict__ Wq, const float* __restrict__ Wk,
                          const float* __restrict__ Wv, const float* __restrict__ Wo,
                          const float* __restrict__ W1, const float* __restrict__ W2,
                          const int* __restrict__ dst,
                          int nq4, int ntot4, int E) {
    int i = blockIdx.x * blockDim.x + threadIdx.x;
    if (i < ntot4 + 49152) {
        const float* srcp; __nv_bfloat16 *ho, *lo_; size_t r4;
        if (i < ntot4) {
            if (i < nq4) { srcp = qf;  r4 = i;       ho = g_qf_hi;  lo_ = g_qf_lo; }
            else         { srcp = kvf; r4 = i - nq4; ho = g_kvf_hi; lo_ = g_kvf_lo; }
        } else {
            int w = i - ntot4;
            if (w < 16384) {
                int which = w >> 12; r4 = w & 4095;
                if (which == 0)      { srcp = Wq; ho = g_Wq_hi; lo_ = g_Wq_lo; }
                else if (which == 1) { srcp = Wk; ho = g_Wk_hi; lo_ = g_Wk_lo; }
                else if (which == 2) { srcp = Wv; ho = g_Wv_hi; lo_ = g_Wv_lo; }
                else                 { srcp = Wo; ho = g_Wo_hi; lo_ = g_Wo_lo; }
            } else if (w < 32768) { srcp = W1; r4 = w - 16384; ho = g_W1_hi; lo_ = g_W1_lo; }
            else                  { srcp = W2; r4 = w - 32768; ho = g_W2_hi; lo_ = g_W2_lo; }
        }
        float4 x = *(const float4*)(srcp + r4 * 4);
        __nv_bfloat16 h[4], l[4];
        f32_hilo(x.x, h[0], l[0]); f32_hilo(x.y, h[1], l[1]);
        f32_hilo(x.z, h[2], l[2]); f32_hilo(x.w, h[3], l[3]);
        *(uint2*)(ho  + r4 * 4) = *(uint2*)h;
        *(uint2*)(lo_ + r4 * 4) = *(uint2*)l;
        return;
    }
    int e = i - ntot4 - 49152;
    if (e < E) atomicAdd(&g_cnt[dst[e]], 1);
}

// ---------------- tensor-core GEMM mainloop (acc in registers) -----------------
#define KSTB  80
#define BUF   (128 * KSTB)                 // 10240 bytes
#define STAGE (4 * BUF)                    // 40960 per stage
#define GEMM_SMEM (2 * STAGE)              // 81920 bytes

__device__ __forceinline__ void stage32(uint32_t sbase, int tid,
    const __nv_bfloat16* __restrict__ Ahi, const __nv_bfloat16* __restrict__ Alo,
    const __nv_bfloat16* __restrict__ Bhi, const __nv_bfloat16* __restrict__ Blo,
    int row0, int c0, int kc, int Kstride, int Nrows) {
#pragma unroll
    for (int j = 0; j < 8; j++) {
        int id  = tid + (j << 8);
        int buf = id >> 9;
        int rem = id & 511;
        int r   = rem >> 2;
        int c16 = rem & 3;
        const __nv_bfloat16* g;
        int rg;
        if (buf == 0)      { g = Ahi; rg = min(row0 + r, Nrows - 1); }
        else if (buf == 1) { g = Alo; rg = min(row0 + r, Nrows - 1); }
        else if (buf == 2) { g = Bhi; rg = c0 + r; }
        else               { g = Blo; rg = c0 + r; }
        uint32_t daddr = sbase + buf * BUF + r * KSTB + c16 * 16;
        unsigned long long gsrc =
            (unsigned long long)__cvta_generic_to_global(g + (size_t)rg * Kstride + kc + c16 * 8);
        asm volatile("cp.async.cg.shared.global [%0], [%1], 16;"
                     :: "r"(daddr), "l"(gsrc) : "memory");
    }
}

__device__ __forceinline__ void gemm_compute(
    char* smem,
    const __nv_bfloat16* __restrict__ Ahi, const __nv_bfloat16* __restrict__ Alo,
    const __nv_bfloat16* __restrict__ Bhi, const __nv_bfloat16* __restrict__ Blo,
    int Nrows, int Kstride, int Klen, int row0, int c0,
    float (&acc)[4][4][4]) {
    const uint32_t sb = smem_u32(smem);
    const int tid  = threadIdx.x;
    const int wid  = tid >> 5;
    const int lane = tid & 31;
    const int wr   = wid >> 2;
    const int wc   = wid & 3;

    const int a_off = ((lane & 7) + ((lane >> 3) & 1) * 8) * KSTB + (lane >> 4) * 16;
    const int b_off = ((lane & 7) + (lane >> 4) * 8) * KSTB + ((lane >> 3) & 1) * 16;

#pragma unroll
    for (int mi = 0; mi < 4; mi++)
#pragma unroll
        for (int ni = 0; ni < 4; ni++)
#pragma unroll
            for (int t = 0; t < 4; t++) acc[mi][ni][t] = 0.f;

    const int NC = Klen >> 5;
    stage32(sb, tid, Ahi, Alo, Bhi, Blo, row0, c0, 0, Kstride, Nrows);
    asm volatile("cp.async.commit_group;" ::: "memory");

    for (int ch = 0; ch < NC; ch++) {
        if (ch + 1 < NC) {
            stage32(sb + ((ch + 1) & 1) * STAGE, tid, Ahi, Alo, Bhi, Blo,
                    row0, c0, (ch + 1) << 5, Kstride, Nrows);
            asm volatile("cp.async.commit_group;" ::: "memory");
            asm volatile("cp.async.wait_group 1;" ::: "memory");
        } else {
            asm volatile("cp.async.wait_group 0;" ::: "memory");
        }
        __syncthreads();

        const uint32_t uAh = sb + (ch & 1) * STAGE;
        const uint32_t uAl = uAh + BUF;
        const uint32_t uBh = uAh + 2 * BUF;
        const uint32_t uBl = uAh + 3 * BUF;

#pragma unroll
        for (int ks = 0; ks < 2; ks++) {
            const int kbyte = ks << 5;
            uint32_t bh[2][4], bl[2][4];
#pragma unroll
            for (int p = 0; p < 2; p++) {
                uint32_t bbase = (uint32_t)((wc * 32 + p * 16) * KSTB + kbyte + b_off);
                ldsm4(bh[p], uBh + bbase);
                ldsm4(bl[p], uBl + bbase);
            }
#pragma unroll
            for (int mi = 0; mi < 4; mi++) {
                uint32_t abase = (uint32_t)((wr * 64 + mi * 16) * KSTB + kbyte + a_off);
                uint32_t ah[4], al[4];
                ldsm4(ah, uAh + abase);
                ldsm4(al, uAl + abase);
#pragma unroll
                for (int ni = 0; ni < 4; ni++) {
                    const uint32_t* pbh = &bh[ni >> 1][(ni & 1) * 2];
                    const uint32_t* pbl = &bl[ni >> 1][(ni & 1) * 2];
                    mma16816(acc[mi][ni], ah, pbh);
                    mma16816(acc[mi][ni], ah, pbl);
                    mma16816(acc[mi][ni], al, pbh);
                }
            }
        }
        __syncthreads();
    }
}

template<bool BIAS, bool RELU, bool WF32, bool WHILO>
__device__ __forceinline__ void gemm_body(
    char* smem,
    const __nv_bfloat16* __restrict__ Ahi, const __nv_bfloat16* __restrict__ Alo,
    const __nv_bfloat16* __restrict__ Bhi, const __nv_bfloat16* __restrict__ Blo,
    const float* __restrict__ bias,
    float* __restrict__ outf, __nv_bfloat16* __restrict__ outhi,
    __nv_bfloat16* __restrict__ outlo, int Nrows, int C,
    int Kstride, int Klen, int row0, int c0) {
    float acc[4][4][4];
    gemm_compute(smem, Ahi, Alo, Bhi, Blo, Nrows, Kstride, Klen, row0, c0, acc);

    const int tid  = threadIdx.x;
    const int wid  = tid >> 5;
    const int lane = tid & 31;
    const int wr   = wid >> 2;
    const int wc   = wid & 3;
    const int gq   = lane >> 2;
    const int tg   = lane & 3;

#pragma unroll
    for (int mi = 0; mi < 4; mi++) {
#pragma unroll
        for (int half = 0; half < 2; half++) {
            int r = row0 + wr * 64 + mi * 16 + gq + half * 8;
            if (r >= Nrows) continue;
#pragma unroll
            for (int ni = 0; ni < 4; ni++) {
                int c = c0 + wc * 32 + ni * 8 + tg * 2;
                float v0 = acc[mi][ni][half * 2 + 0];
                float v1 = acc[mi][ni][half * 2 + 1];
                if (BIAS && bias != nullptr) { v0 += bias[c]; v1 += bias[c + 1]; }
                if (RELU) { v0 = fmaxf(v0, 0.f); v1 = fmaxf(v1, 0.f); }
                size_t o = (size_t)r * C + c;
                if (WF32) *(float2*)(outf + o) = make_float2(v0, v1);
                if (WHILO) {
                    __nv_bfloat16 h0, l0, h1, l1;
                    f32_hilo(v0, h0, l0); f32_hilo(v1, h1, l1);
                    __nv_bfloat162 hh; hh.x = h0; hh.y = h1;
                    __nv_bfloat162 ll; ll.x = l0; ll.y = l1;
                    *(__nv_bfloat162*)(outhi + o) = hh;
                    *(__nv_bfloat162*)(outlo + o) = ll;
                }
            }
        }
    }
}

// SPLITK4: grid.y = K-quarter; partial fp32 sums to outf + kh*kslice; bias only in slice 0.
template<bool BIAS, bool RELU, bool WF32, bool WHILO, bool SPLITK4>
__global__ void __launch_bounds__(256, 2)
gemm_mma(const __nv_bfloat16* __restrict__ Ahi, const __nv_bfloat16* __restrict__ Alo,
         const __nv_bfloat16* __restrict__ Bhi, const __nv_bfloat16* __restrict__ Blo,
         const float* __restrict__ bias,
         float* __restrict__ outf, size_t kslice,
         __nv_bfloat16* __restrict__ outhi, __nv_bfloat16* __restrict__ outlo,
         int Nrows, int C, int Kstride, int Klen) {
    extern __shared__ char smem[];
    if (SPLITK4) {
        int kh   = blockIdx.y;
        int koff = kh * Klen;
        float* of = outf + (size_t)kh * kslice;
        const float* b = kh ? nullptr : bias;
        gemm_body<BIAS, RELU, WF32, WHILO>(smem, Ahi + koff, Alo + koff,
                                           Bhi + koff, Blo + koff, b,
                                           of, outhi, outlo, Nrows, C,
                                           Kstride, Klen, blockIdx.x * 128, 0);
    } else {
        gemm_body<BIAS, RELU, WF32, WHILO>(smem, Ahi, Alo, Bhi, Blo, bias,
                                           outf, outhi, outlo, Nrows, C,
                                           Kstride, Klen, blockIdx.x * 128,
                                           blockIdx.y * 128);
    }
}

// ---------------- fused Wo GEMM + residual + LN1 -------------------------------
__global__ void __launch_bounds__(256, 2)
wo_ln(const float* __restrict__ qfeat, const float* __restrict__ gamma,
      const float* __restrict__ beta, int NQ) {
    extern __shared__ char smem[];
    const int row0 = blockIdx.x * 128;
    float acc[4][4][4];
    gemm_compute(smem, g_attn_hi, g_attn_lo, g_Wo_hi, g_Wo_lo, NQ, D, D, row0, 0, acc);

    const int tid  = threadIdx.x;
    const int wid  = tid >> 5;
    const int lane = tid & 31;
    const int wr   = wid >> 2;
    const int wc   = wid & 3;
    const int gq   = lane >> 2;
    const int tg   = lane & 3;

    float* sf = (float*)smem;              // 128 x 132 fp32 tile
#pragma unroll
    for (int mi = 0; mi < 4; mi++)
#pragma unroll
        for (int half = 0; half < 2; half++) {
            int r = wr * 64 + mi * 16 + gq + half * 8;
#pragma unroll
            for (int ni = 0; ni < 4; ni++) {
                int c = wc * 32 + ni * 8 + tg * 2;
                sf[r * 132 + c]     = acc[mi][ni][half * 2 + 0];
                sf[r * 132 + c + 1] = acc[mi][ni][half * 2 + 1];
            }
        }
    __syncthreads();

    float4 g4 = *(const float4*)(gamma + lane * 4);
    float4 b4 = *(const float4*)(beta  + lane * 4);
    for (int rr = 0; rr < 16; rr++) {
        int r  = wid * 16 + rr;
        int gr = row0 + r;
        if (gr >= NQ) break;
        float4 x = *(const float4*)(sf + r * 132 + lane * 4);
        float4 qv = *(const float4*)(qfeat + (size_t)gr * D + lane * 4);
        x.x += qv.x; x.y += qv.y; x.z += qv.z; x.w += qv.w;
        float s  = x.x + x.y + x.z + x.w;
        float s2 = x.x * x.x + x.y * x.y + x.z * x.z + x.w * x.w;
#pragma unroll
        for (int o = 16; o; o >>= 1) {
            s  += __shfl_xor_sync(0xffffffffu, s,  o);
            s2 += __shfl_xor_sync(0xffffffffu, s2, o);
        }
        float mu  = s * (1.f / 128.f);
        float var = s2 * (1.f / 128.f) - mu * mu;
        float inv = rsqrtf(var + 1e-5f);
        float4 y;
        y.x = (x.x - mu) * inv * g4.x + b4.x;
        y.y = (x.y - mu) * inv * g4.y + b4.y;
        y.z = (x.z - mu) * inv * g4.z + b4.z;
        y.w = (x.w - mu) * inv * g4.w + b4.w;
        size_t o_ = (size_t)gr * D + lane * 4;
        *(float4*)(g_feat + o_) = y;
        __nv_bfloat16 h[4], l[4];
        f32_hilo(y.x, h[0], l[0]); f32_hilo(y.y, h[1], l[1]);
        f32_hilo(y.z, h[2], l[2]); f32_hilo(y.w, h[3], l[3]);
        *(uint2*)(g_feat_hi + o_) = *(uint2*)h;
        *(uint2*)(g_feat_lo + o_) = *(uint2*)l;
    }
}

// CSR scan as a device function (256 threads); also re-zeroes cnt for replay
__device__ void scan_body(char* smem_raw, int* cnt, int* off, int* cursor, int n) {
    int* sc = (int*)smem_raw;
    __shared__ int wsum[8];
    const int tid  = threadIdx.x;
    const int lane = tid & 31;
    const int wid  = tid >> 5;

    for (int i = tid; i < n; i += 256) { sc[i] = cnt[i]; cnt[i] = 0; }
    __syncthreads();

    const int chunk = (n + 255) >> 8;
    const int s = min(tid * chunk, n);
    const int e = min(s + chunk, n);

    int sum = 0;
    for (int i = s; i < e; i++) sum += sc[i];

    int x = sum;
#pragma unroll
    for (int o = 1; o < 32; o <<= 1) {
        int y = __shfl_up_sync(0xffffffffu, x, o);
        if (lane >= o) x += y;
    }
    if (lane == 31) wsum[wid] = x;
    __syncthreads();
    int pre = 0;
    for (int w = 0; w < wid; w++) pre += wsum[w];

    int run = x - sum + pre;
    for (int i = s; i < e; i++) {
        int c = sc[i];
        sc[i] = run;
        run += c;
    }
    __syncthreads();
    for (int i = tid; i < n; i += 256) {
        int v = sc[i];
        off[i] = v;
        cursor[i] = v;
    }
    if (tid == 255) off[n] = run;
}

// fused q/k/v projections + single scan block (1D grid: 3*MT GEMM blocks + 1)
__global__ void __launch_bounds__(256, 2)
proj_scan(int NQ, int NKV, int MT, int* cnt, int* off, int* cursor) {
    extern __shared__ char smem[];
    int b = blockIdx.x;
    if (b < 3 * MT) {
        int which = b / MT;
        int row0  = (b % MT) * 128;
        if (which == 0) {
            if (row0 >= NQ) return;
            gemm_body<false, false, true, false>(smem, g_qf_hi, g_qf_lo, g_Wq_hi, g_Wq_lo,
                                                 nullptr, g_q, nullptr, nullptr, NQ, D, D, D, row0, 0);
        } else if (which == 1) {
            if (row0 >= NKV) return;
            gemm_body<false, false, true, false>(smem, g_kvf_hi, g_kvf_lo, g_Wk_hi, g_Wk_lo,
                                                 nullptr, g_k, nullptr, nullptr, NKV, D, D, D, row0, 0);
        } else {
            if (row0 >= NKV) return;
            gemm_body<false, false, true, false>(smem, g_kvf_hi, g_kvf_lo, g_Wv_hi, g_Wv_lo,
                                                 nullptr, g_v, nullptr, nullptr, NKV, D, D, D, row0, 0);
        }
    } else {
        scan_body(smem, cnt, off, cursor, NQ);
    }
}

// ---------------- CSR fill: 4 edges/thread for atomic MLP ---------------------
__global__ void fill_kernel(const int* __restrict__ dst, const int* __restrict__ src,
                            int* __restrict__ cursor, int* __restrict__ slist, int E) {
    int S = (E + 3) >> 2;
    int t = blockIdx.x * blockDim.x + threadIdx.x;
    if (t >= S) return;
    int e0 = t, e1 = t + S, e2 = t + 2 * S, e3 = t + 3 * S;
    bool b1 = e1 < E, b2 = e2 < E, b3 = e3 < E;
    int d0 = dst[e0];
    int d1 = b1 ? dst[e1] : 0;
    int d2 = b2 ? dst[e2] : 0;
    int d3 = b3 ? dst[e3] : 0;
    int r0 = src[e0];
    int r1 = b1 ? src[e1] : 0;
    int r2 = b2 ? src[e2] : 0;
    int r3 = b3 ? src[e3] : 0;
    int p0 = atomicAdd(&cursor[d0], 1);
    int p1 = b1 ? atomicAdd(&cursor[d1], 1) : 0;
    int p2 = b2 ? atomicAdd(&cursor[d2], 1) : 0;
    int p3 = b3 ? atomicAdd(&cursor[d3], 1) : 0;
    slist[p0] = r0;
    if (b1) slist[p1] = r1;
    if (b2) slist[p2] = r2;
    if (b3) slist[p3] = r3;
}

// ---------------- fused edge-softmax attention (two warps per dst node) -------
#define ASHIFT 20.0f
__global__ __launch_bounds__(256)
void attn_gather(const float* __restrict__ k, const float* __restrict__ q,
                 const float* __restrict__ v, const int* __restrict__ slist,
                 const int* __restrict__ off,
                 __nv_bfloat16* __restrict__ out_hi, __nv_bfloat16* __restrict__ out_lo,
                 int NQ) {
    __shared__ float red[8][5 * 32];
    int gwarp = (blockIdx.x * blockDim.x + threadIdx.x) >> 5;
    int lane  = threadIdx.x & 31;
    int bwid  = threadIdx.x >> 5;
    int node  = gwarp >> 1;
    int half  = gwarp & 1;
    if (node >= NQ) return;

    float4 qv = *(const float4*)(q + (size_t)node * D + lane * 4);
    int i0 = off[node], i1 = off[node + 1];
    int mid = i0 + ((i1 - i0) >> 1);
    int lo  = half ? mid : i0;
    int hi  = half ? i1  : mid;

    float sA = 0.f, sB = 0.f;
    float4 aA = make_float4(0.f, 0.f, 0.f, 0.f);
    float4 aB = make_float4(0.f, 0.f, 0.f, 0.f);

    int i = lo;
    for (; i + 1 < hi; i += 2) {
        int s0 = slist[i], s1 = slist[i + 1];
        float4 k0 = *(const float4*)(k + (size_t)s0 * D + lane * 4);
        float4 k1 = *(const float4*)(k + (size_t)s1 * D + lane * 4);
        float4 v0 = *(const float4*)(v + (size_t)s0 * D + lane * 4);
        float4 v1 = *(const float4*)(v + (size_t)s1 * D + lane * 4);
        float d0 = k0.x * qv.x + k0.y * qv.y + k0.z * qv.z + k0.w * qv.w;
        float d1 = k1.x * qv.x + k1.y * qv.y + k1.z * qv.z + k1.w * qv.w;
        d0 += __shfl_xor_sync(0xffffffffu, d0, 1);
        d1 += __shfl_xor_sync(0xffffffffu, d1, 1);
        d0 += __shfl_xor_sync(0xffffffffu, d0, 2);
        d1 += __shfl_xor_sync(0xffffffffu, d1, 2);
        float p0 = __expf(d0 * 0.25f - ASHIFT);
        float p1 = __expf(d1 * 0.25f - ASHIFT);
        sA += p0;
        sB += p1;
        aA.x += p0 * v0.x;  aB.x += p1 * v1.x;
        aA.y += p0 * v0.y;  aB.y += p1 * v1.y;
        aA.z += p0 * v0.z;  aB.z += p1 * v1.z;
        aA.w += p0 * v0.w;  aB.w += p1 * v1.w;
    }
    if (i < hi) {
        int s0 = slist[i];
        float4 k0 = *(const float4*)(k + (size_t)s0 * D + lane * 4);
        float4 v0 = *(const float4*)(v + (size_t)s0 * D + lane * 4);
        float d0 = k0.x * qv.x + k0.y * qv.y + k0.z * qv.z + k0.w * qv.w;
        d0 += __shfl_xor_sync(0xffffffffu, d0, 1);
        d0 += __shfl_xor_sync(0xffffffffu, d0, 2);
        float p0 = __expf(d0 * 0.25f - ASHIFT);
        sA += p0;
        aA.x += p0 * v0.x; aA.y += p0 * v0.y;
        aA.z += p0 * v0.z; aA.w += p0 * v0.w;
    }
    float s = sA + sB;
    float4 acc;
    acc.x = aA.x + aB.x;
    acc.y = aA.y + aB.y;
    acc.z = aA.z + aB.z;
    acc.w = aA.w + aB.w;

    float* slot = red[bwid];
    slot[0 * 32 + lane] = s;
    slot[1 * 32 + lane] = acc.x;
    slot[2 * 32 + lane] = acc.y;
    slot[3 * 32 + lane] = acc.z;
    slot[4 * 32 + lane] = acc.w;
    __syncthreads();
    if (half == 0) {
        const float* part = red[bwid ^ 1];
        s     += part[0 * 32 + lane];
        acc.x += part[1 * 32 + lane];
        acc.y += part[2 * 32 + lane];
        acc.z += part[3 * 32 + lane];
        acc.w += part[4 * 32 + lane];

        float inv = (s > 0.f) ? (1.f / s) : 0.f;
        float4 o = make_float4(acc.x * inv, acc.y * inv, acc.z * inv, acc.w * inv);
        __nv_bfloat16 h[4], l[4];
        f32_hilo(o.x, h[0], l[0]); f32_hilo(o.y, h[1], l[1]);
        f32_hilo(o.z, h[2], l[2]); f32_hilo(o.w, h[3], l[3]);
        size_t ob = (size_t)node * D + lane * 4;
        *(uint2*)(out_hi + ob) = *(uint2*)h;
        *(uint2*)(out_lo + ob) = *(uint2*)l;
    }
}

// ---------------- residual add (1 + 4 split-K slices) + layernorm -------------
__global__ void add_ln_kernel(const float* __restrict__ a, const float* __restrict__ ffs,
                              size_t kslice,
                              const float* __restrict__ gamma, const float* __restrict__ beta,
                              float* __restrict__ out) {
    int row = blockIdx.x;
    int t   = threadIdx.x;
    size_t idx = (size_t)row * D + t;
    float x = a[idx] + ffs[idx] + ffs[idx + kslice] +
              ffs[idx + 2 * kslice] + ffs[idx + 3 * kslice];
    float s = x, s2 = x * x;
#pragma unroll
    for (int off = 16; off; off >>= 1) {
        s  += __shfl_xor_sync(0xffffffffu, s,  off);
        s2 += __shfl_xor_sync(0xffffffffu, s2, off);
    }
    __shared__ float ps[4], ps2[4];
    if ((t & 31) == 0) { ps[t >> 5] = s; ps2[t >> 5] = s2; }
    __syncthreads();
    s  = ps[0]  + ps[1]  + ps[2]  + ps[3];
    s2 = ps2[0] + ps2[1] + ps2[2] + ps2[3];
    float mu  = s * (1.f / 128.f);
    float var = s2 * (1.f / 128.f) - mu * mu;
    float invs = rsqrtf(var + 1e-5f);
    out[idx] = (x - mu) * invs * gamma[t] + beta[t];
}

// ---------------- launch -----------------------------------------------------
extern "C" void kernel_launch(void* const* d_in, const int* in_sizes, int n_in,
                              void* d_out, int out_size) {
    const float* q_feat  = (const float*)d_in[0];
    const float* kv_feat = (const float*)d_in[1];
    const int*   src     = (const int*)d_in[2];
    const int*   dst     = (const int*)d_in[3];
    const float* Wq      = (const float*)d_in[4];
    const float* Wk      = (const float*)d_in[5];
    const float* Wv      = (const float*)d_in[6];
    const float* Wo      = (const float*)d_in[7];
    const float* W1      = (const float*)d_in[8];
    const float* bf1     = (const float*)d_in[9];
    const float* W2      = (const float*)d_in[10];
    const float* bf2     = (const float*)d_in[11];
    const float* ln1_g   = (const float*)d_in[12];
    const float* ln1_b   = (const float*)d_in[13];
    const float* ln2_g   = (const float*)d_in[14];
    const float* ln2_b   = (const float*)d_in[15];

    const int NQ  = in_sizes[0] / D;
    const int NKV = in_sizes[1] / D;
    const int E   = in_sizes[2];

    float *qp, *kp, *vp, *featp, *ffsp;
    __nv_bfloat16 *ath, *atl, *fth, *ftl, *hdh, *hdl;
    __nv_bfloat16 *w1h, *w1l, *w2h, *w2l;
    int *cntp, *offp, *curp, *slistp;
    cudaGetSymbolAddress((void**)&qp,    g_q);
    cudaGetSymbolAddress((void**)&kp,    g_k);
    cudaGetSymbolAddress((void**)&vp,    g_v);
    cudaGetSymbolAddress((void**)&featp, g_feat);
    cudaGetSymbolAddress((void**)&ffsp,  g_ffs);
    cudaGetSymbolAddress((void**)&ath,   g_attn_hi); cudaGetSymbolAddress((void**)&atl, g_attn_lo);
    cudaGetSymbolAddress((void**)&fth,   g_feat_hi); cudaGetSymbolAddress((void**)&ftl, g_feat_lo);
    cudaGetSymbolAddress((void**)&hdh,   g_hid_hi);  cudaGetSymbolAddress((void**)&hdl, g_hid_lo);
    cudaGetSymbolAddress((void**)&w1h,   g_W1_hi);   cudaGetSymbolAddress((void**)&w1l, g_W1_lo);
    cudaGetSymbolAddress((void**)&w2h,   g_W2_hi);   cudaGetSymbolAddress((void**)&w2l, g_W2_lo);
    cudaGetSymbolAddress((void**)&cntp,  g_cnt);
    cudaGetSymbolAddress((void**)&offp,  g_off);
    cudaGetSymbolAddress((void**)&curp,  g_cursor);
    cudaGetSymbolAddress((void**)&slistp, g_slist);

    cudaFuncSetAttribute(proj_scan,
                         cudaFuncAttributeMaxDynamicSharedMemorySize, GEMM_SMEM);
    cudaFuncSetAttribute(wo_ln,
                         cudaFuncAttributeMaxDynamicSharedMemorySize, GEMM_SMEM);
    cudaFuncSetAttribute(gemm_mma<true,  true,  false, true,  false>,
                         cudaFuncAttributeMaxDynamicSharedMemorySize, GEMM_SMEM);
    cudaFuncSetAttribute(gemm_mma<true,  false, true,  false, true>,
                         cudaFuncAttributeMaxDynamicSharedMemorySize, GEMM_SMEM);

    const int MTq  = (NQ + 127) / 128;
    const int MTkv = (NKV + 127) / 128;
    const int MTmax = MTq > MTkv ? MTq : MTkv;
    const size_t kslice = (size_t)NQ_MAX * D;

    // (0) fused conversions (vectorized) + histogram
    int nq4   = NQ * D / 4;
    int ntot4 = (NQ + NKV) * D / 4;
    int ch_threads = ntot4 + 49152 + E;
    conv_hist<<<(ch_threads + 255) / 256, 256>>>(q_feat, kv_feat, Wq, Wk, Wv, Wo, W1, W2,
                                                 dst, nq4, ntot4, E);
    // (1) fused q/k/v projections + scan
    proj_scan<<<3 * MTmax + 1, 256, GEMM_SMEM>>>(NQ, NKV, MTmax, cntp, offp, curp);
    // (2) CSR fill (4 edges/thread)
    int fthreads = (E + 3) / 4;
    fill_kernel<<<(fthreads + 255) / 256, 256>>>(dst, src, curp, slistp, E);
    // (3) fused edge-softmax attention (2 warps/node)  <- ncu capture slot
    int ablocks = (NQ * 2 * 32 + 255) / 256;
    attn_gather<<<ablocks, 256>>>(kp, qp, vp, slistp, offp, ath, atl, NQ);

    // (4) fused Wo GEMM + residual + LN1
    wo_ln<<<MTq, 256, GEMM_SMEM>>>(q_feat, ln1_g, ln1_b, NQ);

    // FFN: W1 (no split, 4 col tiles), W2 (split-K: 4 slices of 128)
    gemm_mma<true, true, false, true, false><<<dim3(MTq, 4), 256, GEMM_SMEM>>>(
        fth, ftl, w1h, w1l, bf1, nullptr, 0, hdh, hdl, NQ, DF, D, D);
    gemm_mma<true, false, true, false, true><<<dim3(MTq, 4), 256, GEMM_SMEM>>>(
        hdh, hdl, w2h, w2l, bf2, ffsp, kslice, nullptr, nullptr, NQ, D, DF, 128);

    // final residual LN -> output
    add_ln_kernel<<<NQ, 128>>>(featp, ffsp, kslice, ln2_g, ln2_b, (float*)d_out);
}